// round 12
// baseline (speedup 1.0000x reference)
#include <cuda_runtime.h>
#include <cuda_bf16.h>

namespace {
constexpr int Bc = 2;
constexpr int Sc = 2048;
constexpr int DM = 1024;
constexpr int Hc = 16;
constexpr int BH = Bc * Hc;
constexpr int MROWS = Bc * Sc;
constexpr float SCALE = 0.125f;
constexpr float NEG_BIG = -3.0e38f;
constexpr int QSTR = 72;                 // attn smem row stride (bf16)
constexpr int KSTAGE = 64 * QSTR;        // elements per K/V stage buffer
constexpr int PROJ_STAGE = 10240;        // bytes: 128 rows * 80B
constexpr int PROJ_SMEM = 81920;         // 4 buffers * 2 stages * 10240
}

// Pre-converted packed bf16 hi/lo buffers
__device__ __align__(16) unsigned g_xh[3][MROWS * 512];
__device__ __align__(16) unsigned g_xl[3][MROWS * 512];
__device__ __align__(16) unsigned g_wh[4][DM * 512];
__device__ __align__(16) unsigned g_wl[4][DM * 512];
__device__ __align__(16) unsigned g_qhh[BH * Sc * 32];
__device__ __align__(16) unsigned g_qhl[BH * Sc * 32];
__device__ __align__(16) unsigned g_khh[BH * Sc * 32];
__device__ __align__(16) unsigned g_khl[BH * Sc * 32];
__device__ __align__(16) __nv_bfloat16 g_vth[BH * 64 * Sc];
__device__ __align__(16) __nv_bfloat16 g_vtl[BH * 64 * Sc];
__device__ __align__(16) unsigned g_ch[MROWS * 512];
__device__ __align__(16) unsigned g_cl[MROWS * 512];

// ---------------- helpers ----------------
__device__ __forceinline__ void mma16816(float* d, const unsigned* a, const unsigned* b) {
    asm volatile(
        "mma.sync.aligned.m16n8k16.row.col.f32.bf16.bf16.f32 "
        "{%0,%1,%2,%3}, {%4,%5,%6,%7}, {%8,%9}, {%0,%1,%2,%3};"
        : "+f"(d[0]), "+f"(d[1]), "+f"(d[2]), "+f"(d[3])
        : "r"(a[0]), "r"(a[1]), "r"(a[2]), "r"(a[3]), "r"(b[0]), "r"(b[1]));
}
__device__ __forceinline__ void split_pack2(float a, float b, unsigned& hi, unsigned& lo) {
    __nv_bfloat16 ah = __float2bfloat16_rn(a);
    __nv_bfloat16 bh = __float2bfloat16_rn(b);
    __nv_bfloat16 al = __float2bfloat16_rn(a - __bfloat162float(ah));
    __nv_bfloat16 bl = __float2bfloat16_rn(b - __bfloat162float(bh));
    hi = (unsigned)__bfloat16_as_ushort(ah) | ((unsigned)__bfloat16_as_ushort(bh) << 16);
    lo = (unsigned)__bfloat16_as_ushort(al) | ((unsigned)__bfloat16_as_ushort(bl) << 16);
}
__device__ __forceinline__ unsigned scvta(const void* p) {
    return (unsigned)__cvta_generic_to_shared(p);
}
__device__ __forceinline__ void ldsm4(unsigned* r, unsigned a) {
    asm volatile("ldmatrix.sync.aligned.m8n8.x4.shared.b16 {%0,%1,%2,%3}, [%4];"
                 : "=r"(r[0]), "=r"(r[1]), "=r"(r[2]), "=r"(r[3]) : "r"(a));
}
__device__ __forceinline__ void cpa16(unsigned s, const void* g) {
    asm volatile("cp.async.cg.shared.global [%0], [%1], 16;" :: "r"(s), "l"(g) : "memory");
}
#define CPCOMMIT() asm volatile("cp.async.commit_group;" ::: "memory")
#define CPWAIT1()  asm volatile("cp.async.wait_group 1;" ::: "memory")
#define CPWAIT0()  asm volatile("cp.async.wait_group 0;" ::: "memory")

// ---------------------------------------------------------------------------
// One-time converts
// ---------------------------------------------------------------------------
__global__ __launch_bounds__(256) void conv_x(const float* __restrict__ q,
                                              const float* __restrict__ k,
                                              const float* __restrict__ v) {
    size_t idx = (size_t)blockIdx.x * 256 + threadIdx.x;
    int sel = (int)(idx >> 21);
    size_t r = idx & ((1u << 21) - 1);
    const float* X = sel == 0 ? q : sel == 1 ? k : v;
    float2 xv = *(const float2*)&X[2 * r];
    unsigned hi, lo;
    split_pack2(xv.x, xv.y, hi, lo);
    g_xh[sel][r] = hi;
    g_xl[sel][r] = lo;
}

__global__ __launch_bounds__(256) void conv_w(const float* __restrict__ wq,
                                              const float* __restrict__ wk,
                                              const float* __restrict__ wv,
                                              const float* __restrict__ wo) {
    const int z = blockIdx.z;
    const float* W = z == 0 ? wq : z == 1 ? wk : z == 2 ? wv : wo;
    __shared__ float t[32][33];
    const int tid = threadIdx.x, tx = tid & 31, ty = tid >> 5;
    const int k0 = blockIdx.y * 32, n0 = blockIdx.x * 32;
#pragma unroll
    for (int i = 0; i < 4; i++)
        t[ty + i * 8][tx] = W[(size_t)(k0 + ty + i * 8) * DM + n0 + tx];
    __syncthreads();
#pragma unroll
    for (int i = 0; i < 2; i++) {
        int e = tid + i * 256, n = e >> 4, c = e & 15;
        unsigned hi, lo;
        split_pack2(t[2 * c][n], t[2 * c + 1][n], hi, lo);
        size_t o = (size_t)(n0 + n) * 512 + (k0 >> 1) + c;
        g_wh[z][o] = hi;
        g_wl[z][o] = lo;
    }
}

// ---------------------------------------------------------------------------
// HMMA projection GEMM, cp.async double-buffered, dynamic smem.
// ---------------------------------------------------------------------------
__global__ __launch_bounds__(256, 2) void proj_mma(
    const float* __restrict__ bq, const float* __restrict__ bk,
    const float* __restrict__ bv, const float* __restrict__ bo,
    float* __restrict__ extout, int selArg) {
    const int sel = (selArg < 0) ? (int)blockIdx.z : selArg;
    const unsigned* Aph = (sel < 3) ? g_xh[sel] : g_ch;
    const unsigned* Apl = (sel < 3) ? g_xl[sel] : g_cl;
    const unsigned* Bph = g_wh[sel];
    const unsigned* Bpl = g_wl[sel];
    const float* bias = sel == 0 ? bq : sel == 1 ? bk : sel == 2 ? bv : bo;

    extern __shared__ char psm[];
    // byte offsets: Ah st*10240; Al 20480+; Bh 40960+; Bl 61440+
    const int tid = threadIdx.x;
    const int wid = tid >> 5, lane = tid & 31;
    const int g = lane >> 2, tig = lane & 3;
    const int wm = wid & 3, wn = wid >> 2;
    const int m0 = blockIdx.y * 128, n0 = blockIdx.x * 128;
    const int l7 = lane & 7, b8 = (lane >> 3) & 1, b16 = (lane >> 4) & 1;

    const unsigned sbase = scvta(psm);
    const unsigned aA = sbase + (unsigned)((wm * 32 + l7 + b8 * 8) * 80 + b16 * 16);
    const unsigned aB = sbase + 40960u + (unsigned)((wn * 64 + l7 + b16 * 8) * 80 + b8 * 16);

    float acc[2][8][4];
#pragma unroll
    for (int mi = 0; mi < 2; mi++)
#pragma unroll
        for (int nt = 0; nt < 8; nt++)
#pragma unroll
            for (int r = 0; r < 4; r++) acc[mi][nt][r] = 0.0f;

    // fill chunk into stage
    auto fill = [&](int kp, int st) {
#pragma unroll
        for (int i = 0; i < 2; i++) {
            int e = tid + i * 256, r = e >> 2, c = e & 3;
            unsigned soff = (unsigned)(st * PROJ_STAGE + r * 80 + c * 16);
            cpa16(sbase + soff,          &Aph[(size_t)(m0 + r) * 512 + kp + c * 4]);
            cpa16(sbase + 20480u + soff, &Apl[(size_t)(m0 + r) * 512 + kp + c * 4]);
            cpa16(sbase + 40960u + soff, &Bph[(size_t)(n0 + r) * 512 + kp + c * 4]);
            cpa16(sbase + 61440u + soff, &Bpl[(size_t)(n0 + r) * 512 + kp + c * 4]);
        }
    };

    fill(0, 0);
    CPCOMMIT();
    for (int c = 0; c < 32; c++) {
        if (c < 31) { fill((c + 1) * 16, (c + 1) & 1); CPCOMMIT(); CPWAIT1(); }
        else        { CPWAIT0(); }
        __syncthreads();
        const unsigned so = (unsigned)((c & 1) * PROJ_STAGE);
#pragma unroll
        for (int ks = 0; ks < 2; ks++) {
            unsigned ah[2][4], al[2][4];
            ldsm4(ah[0], aA + so + ks * 32);
            ldsm4(ah[1], aA + so + 1280 + ks * 32);
            ldsm4(al[0], aA + so + 20480 + ks * 32);
            ldsm4(al[1], aA + so + 20480 + 1280 + ks * 32);
#pragma unroll
            for (int np = 0; np < 4; np++) {
                unsigned b4h[4], b4l[4];
                ldsm4(b4h, aB + so + np * 1280 + ks * 32);
                ldsm4(b4l, aB + so + 20480 + np * 1280 + ks * 32);
#pragma unroll
                for (int j = 0; j < 2; j++) {
                    int nt = np * 2 + j;
#pragma unroll
                    for (int mi = 0; mi < 2; mi++) {
                        mma16816(acc[mi][nt], ah[mi], b4h + 2 * j);
                        mma16816(acc[mi][nt], ah[mi], b4l + 2 * j);
                        mma16816(acc[mi][nt], al[mi], b4h + 2 * j);
                    }
                }
            }
        }
        __syncthreads();
    }

#pragma unroll
    for (int mi = 0; mi < 2; mi++) {
        int rbase = m0 + wm * 32 + mi * 16 + g;
#pragma unroll
        for (int nt = 0; nt < 8; nt++) {
            int col0 = n0 + wn * 64 + nt * 8 + tig * 2;
            float bx = bias[col0], by = bias[col0 + 1];
#pragma unroll
            for (int rr = 0; rr < 2; rr++) {
                int row = rbase + rr * 8;
                float v0 = acc[mi][nt][rr * 2]     + bx;
                float v1 = acc[mi][nt][rr * 2 + 1] + by;
                if (sel == 3) {
                    *(float2*)&extout[(size_t)row * DM + col0] = make_float2(v0, v1);
                    continue;
                }
                int hh = col0 >> 6, d = col0 & 63;
                int b = row >> 11, s = row & 2047;
                if (sel == 2) {
                    __nv_bfloat16 h0 = __float2bfloat16_rn(v0);
                    __nv_bfloat16 h1 = __float2bfloat16_rn(v1);
                    __nv_bfloat16 l0 = __float2bfloat16_rn(v0 - __bfloat162float(h0));
                    __nv_bfloat16 l1 = __float2bfloat16_rn(v1 - __bfloat162float(h1));
                    size_t base = ((size_t)(b * Hc + hh) * 64 + d) * Sc + s;
                    g_vth[base]      = h0;
                    g_vth[base + Sc] = h1;
                    g_vtl[base]      = l0;
                    g_vtl[base + Sc] = l1;
                } else {
                    if (sel == 0) { v0 *= SCALE; v1 *= SCALE; }
                    unsigned hi, lo;
                    split_pack2(v0, v1, hi, lo);
                    size_t idx = ((size_t)(b * Hc + hh) * Sc + s) * 32 + (d >> 1);
                    if (sel == 0) { g_qhh[idx] = hi; g_qhl[idx] = lo; }
                    else          { g_khh[idx] = hi; g_khl[idx] = lo; }
                }
            }
        }
    }
}

// ---------------------------------------------------------------------------
// Fused HMMA attention: Q-frags in registers (pass A), cp.async double buffer.
// ---------------------------------------------------------------------------
__global__ __launch_bounds__(256, 2) void fused_attn(float* __restrict__ attn) {
    extern __shared__ char smraw[];
    __nv_bfloat16* Qh = (__nv_bfloat16*)smraw;       // [128][QSTR]
    __nv_bfloat16* Ql = Qh + 128 * QSTR;
    __nv_bfloat16* Kb = Ql + 128 * QSTR;             // K: [st][hi|lo] 2*2*KSTAGE
    __nv_bfloat16* Vb = Kb + 4 * KSTAGE;             // V: same
    float* mfin = (float*)(Vb + 4 * KSTAGE);
    float* sinv = mfin + 128;
    float* pbuf = sinv + 128;                        // [2][128][2]
    float* obuf = (float*)Kb;                        // alias after last sync

    const int bh = blockIdx.y, q0 = blockIdx.x * 128;
    const int tid = threadIdx.x;
    const int wid = tid >> 5, lane = tid & 31;
    const int g = lane >> 2, tig = lane & 3;
    const int wm = wid & 3, wn = wid >> 2;
    const int l7 = lane & 7, b8 = (lane >> 3) & 1, b16 = (lane >> 4) & 1;

    const unsigned* Qgh = g_qhh + (size_t)bh * Sc * 32;
    const unsigned* Qgl = g_qhl + (size_t)bh * Sc * 32;
    const unsigned* Kgh = g_khh + (size_t)bh * Sc * 32;
    const unsigned* Kgl = g_khl + (size_t)bh * Sc * 32;
    const __nv_bfloat16* Vgh = g_vth + (size_t)bh * 64 * Sc;
    const __nv_bfloat16* Vgl = g_vtl + (size_t)bh * 64 * Sc;

    const unsigned aQh = scvta(&Qh[(wm * 32 + l7 + b8 * 8) * QSTR + b16 * 8]);
    const unsigned aQl = aQh + 128 * QSTR * 2;
    const unsigned aKh = scvta(&Kb[(wn * 32 + l7 + b16 * 8) * QSTR + b8 * 8]);
    const unsigned aKl = aKh + KSTAGE * 2;
    const unsigned aVh = scvta(&Vb[(l7 + b16 * 8) * QSTR + wn * 32 + b8 * 8]);
    const unsigned aVl = aVh + KSTAGE * 2;

    auto fillK = [&](int k0, int st) {
#pragma unroll
        for (int i = 0; i < 2; i++) {
            int e = tid + i * 256, r = e >> 3, c4 = e & 7;
            unsigned sdst = scvta(&Kb[st * 2 * KSTAGE + r * QSTR + c4 * 8]);
            cpa16(sdst,                    &Kgh[(size_t)(k0 + r) * 32 + c4 * 4]);
            cpa16(sdst + KSTAGE * 2,       &Kgl[(size_t)(k0 + r) * 32 + c4 * 4]);
        }
    };
    auto fillV = [&](int k0, int st) {
#pragma unroll
        for (int i = 0; i < 2; i++) {
            int e = tid + i * 256, d = e >> 3, k8 = e & 7;
            unsigned sdst = scvta(&Vb[st * 2 * KSTAGE + d * QSTR + k8 * 8]);
            cpa16(sdst,              &Vgh[(size_t)d * Sc + k0 + k8 * 8]);
            cpa16(sdst + KSTAGE * 2, &Vgl[(size_t)d * Sc + k0 + k8 * 8]);
        }
    };

    // prologue: Q async fill, then K tile 0
#pragma unroll
    for (int i = 0; i < 4; i++) {
        int e = tid + i * 256, r = e >> 3, c4 = e & 7;
        cpa16(scvta(&Qh[r * QSTR + c4 * 8]), &Qgh[(size_t)(q0 + r) * 32 + c4 * 4]);
        cpa16(scvta(&Ql[r * QSTR + c4 * 8]), &Qgl[(size_t)(q0 + r) * 32 + c4 * 4]);
    }
    CPCOMMIT();
    fillK(0, 0);
    CPCOMMIT();
    CPWAIT1();          // Q ready, K0 in flight
    __syncthreads();

    float m_run[4], s_run[4];
#pragma unroll
    for (int i = 0; i < 4; i++) { m_run[i] = NEG_BIG; s_run[i] = 0.0f; }

    // ================= PASS A (Q fragments in registers) =================
    {
        unsigned qfh[2][4][4], qfl[2][4][4];
#pragma unroll
        for (int ks = 0; ks < 4; ks++) {
            ldsm4(qfh[0][ks], aQh + ks * 32);
            ldsm4(qfh[1][ks], aQh + 2304 + ks * 32);
            ldsm4(qfl[0][ks], aQl + ks * 32);
            ldsm4(qfl[1][ks], aQl + 2304 + ks * 32);
        }
        for (int t = 0; t < 32; t++) {
            if (t < 31) { fillK((t + 1) * 64, (t + 1) & 1); CPCOMMIT(); CPWAIT1(); }
            else        { CPWAIT0(); }
            __syncthreads();
            const unsigned kso = (unsigned)((t & 1) * 2 * KSTAGE * 2);

            float lc[2][4][4];
#pragma unroll
            for (int mi = 0; mi < 2; mi++)
#pragma unroll
                for (int nt = 0; nt < 4; nt++)
#pragma unroll
                    for (int r = 0; r < 4; r++) lc[mi][nt][r] = 0.0f;
#pragma unroll
            for (int ks = 0; ks < 4; ks++) {
#pragma unroll
                for (int np = 0; np < 2; np++) {
                    unsigned b4h[4], b4l[4];
                    ldsm4(b4h, aKh + kso + np * 2304 + ks * 32);
                    ldsm4(b4l, aKl + kso + np * 2304 + ks * 32);
#pragma unroll
                    for (int j = 0; j < 2; j++) {
                        int nt = np * 2 + j;
#pragma unroll
                        for (int mi = 0; mi < 2; mi++) {
                            mma16816(lc[mi][nt], qfh[mi][ks], b4h + 2 * j);
                            mma16816(lc[mi][nt], qfh[mi][ks], b4l + 2 * j);
                            mma16816(lc[mi][nt], qfl[mi][ks], b4h + 2 * j);
                        }
                    }
                }
            }
#pragma unroll
            for (int mi = 0; mi < 2; mi++)
#pragma unroll
                for (int rr = 0; rr < 2; rr++) {
                    float tmax = NEG_BIG;
#pragma unroll
                    for (int nt = 0; nt < 4; nt++) {
                        tmax = fmaxf(tmax, lc[mi][nt][rr * 2]);
                        tmax = fmaxf(tmax, lc[mi][nt][rr * 2 + 1]);
                    }
                    tmax = fmaxf(tmax, __shfl_xor_sync(0xffffffffu, tmax, 1));
                    tmax = fmaxf(tmax, __shfl_xor_sync(0xffffffffu, tmax, 2));
                    int ix = mi * 2 + rr;
                    float mold = m_run[ix];
                    float mnew = fmaxf(mold, tmax);
                    float ps = 0.0f;
#pragma unroll
                    for (int nt = 0; nt < 4; nt++) {
                        ps += __expf(lc[mi][nt][rr * 2]     - mnew);
                        ps += __expf(lc[mi][nt][rr * 2 + 1] - mnew);
                    }
                    ps += __shfl_xor_sync(0xffffffffu, ps, 1);
                    ps += __shfl_xor_sync(0xffffffffu, ps, 2);
                    s_run[ix] = s_run[ix] * __expf(mold - mnew) + ps;
                    m_run[ix] = mnew;
                }
            __syncthreads();
        }
    }

    // merge per-warp partials across wn
    if (tig == 0) {
#pragma unroll
        for (int mi = 0; mi < 2; mi++)
#pragma unroll
            for (int rr = 0; rr < 2; rr++) {
                int r = wm * 32 + mi * 16 + g + rr * 8;
                pbuf[wn * 256 + r * 2]     = m_run[mi * 2 + rr];
                pbuf[wn * 256 + r * 2 + 1] = s_run[mi * 2 + rr];
            }
    }
    __syncthreads();
    if (tid < 128) {
        float m0 = pbuf[tid * 2], s0 = pbuf[tid * 2 + 1];
        float m1 = pbuf[256 + tid * 2], s1 = pbuf[256 + tid * 2 + 1];
        float m = fmaxf(m0, m1);
        float s = s0 * __expf(m0 - m) + s1 * __expf(m1 - m);
        mfin[tid] = m;
        sinv[tid] = 1.0f / s;
    }
    __syncthreads();

    float mrow[2][2], svr[2][2];
#pragma unroll
    for (int mi = 0; mi < 2; mi++)
#pragma unroll
        for (int rr = 0; rr < 2; rr++) {
            int r = wm * 32 + mi * 16 + g + rr * 8;
            mrow[mi][rr] = mfin[r];
            svr[mi][rr] = sinv[r];
        }

    float oacc[2][8][4];
#pragma unroll
    for (int mi = 0; mi < 2; mi++)
#pragma unroll
        for (int nt = 0; nt < 8; nt++)
#pragma unroll
            for (int r = 0; r < 4; r++) oacc[mi][nt][r] = 0.0f;

    // ================= PASS B =================
    fillK(0, 0);
    fillV(0, 0);
    CPCOMMIT();
    for (int t = 0; t < 32; t++) {
        if (t < 31) {
            fillK((t + 1) * 64, (t + 1) & 1);
            fillV((t + 1) * 64, (t + 1) & 1);
            CPCOMMIT();
            CPWAIT1();
        } else {
            CPWAIT0();
        }
        __syncthreads();
        const unsigned so = (unsigned)((t & 1) * 2 * KSTAGE * 2);
        const int k0 = t * 64;

        float lc[2][4][4];
#pragma unroll
        for (int mi = 0; mi < 2; mi++)
#pragma unroll
            for (int nt = 0; nt < 4; nt++)
#pragma unroll
                for (int r = 0; r < 4; r++) lc[mi][nt][r] = 0.0f;
#pragma unroll
        for (int ks = 0; ks < 4; ks++) {
            unsigned ah[2][4], al[2][4];
            ldsm4(ah[0], aQh + ks * 32);
            ldsm4(ah[1], aQh + 2304 + ks * 32);
            ldsm4(al[0], aQl + ks * 32);
            ldsm4(al[1], aQl + 2304 + ks * 32);
#pragma unroll
            for (int np = 0; np < 2; np++) {
                unsigned b4h[4], b4l[4];
                ldsm4(b4h, aKh + so + np * 2304 + ks * 32);
                ldsm4(b4l, aKl + so + np * 2304 + ks * 32);
#pragma unroll
                for (int j = 0; j < 2; j++) {
                    int nt = np * 2 + j;
#pragma unroll
                    for (int mi = 0; mi < 2; mi++) {
                        mma16816(lc[mi][nt], ah[mi], b4h + 2 * j);
                        mma16816(lc[mi][nt], ah[mi], b4l + 2 * j);
                        mma16816(lc[mi][nt], al[mi], b4h + 2 * j);
                    }
                }
            }
        }

        unsigned aPh[2][2][4], aPl[2][2][4];
#pragma unroll
        for (int mi = 0; mi < 2; mi++) {
            int row = q0 + wm * 32 + mi * 16 + g;
#pragma unroll
            for (int nt = 0; nt < 4; nt++) {
                float p0 = __expf(lc[mi][nt][0] - mrow[mi][0]) * svr[mi][0];
                float p1 = __expf(lc[mi][nt][1] - mrow[mi][0]) * svr[mi][0];
                float p2 = __expf(lc[mi][nt][2] - mrow[mi][1]) * svr[mi][1];
                float p3 = __expf(lc[mi][nt][3] - mrow[mi][1]) * svr[mi][1];
                int col = k0 + wn * 32 + nt * 8 + tig * 2;
                *(float2*)&attn[((size_t)bh * Sc + row) * Sc + col] = make_float2(p0, p1);
                *(float2*)&attn[((size_t)bh * Sc + row + 8) * Sc + col] = make_float2(p2, p3);
                unsigned h01, l01, h23, l23;
                split_pack2(p0, p1, h01, l01);
                split_pack2(p2, p3, h23, l23);
                int ks2 = nt >> 1, sl = (nt & 1) * 2;
                aPh[mi][ks2][sl]     = h01;
                aPh[mi][ks2][sl + 1] = h23;
                aPl[mi][ks2][sl]     = l01;
                aPl[mi][ks2][sl + 1] = l23;
            }
        }
#pragma unroll
        for (int ks2 = 0; ks2 < 2; ks2++) {
#pragma unroll
            for (int ndp = 0; ndp < 4; ndp++) {
                unsigned b4h[4], b4l[4];
                ldsm4(b4h, aVh + so + ndp * 2304 + ks2 * 32);
                ldsm4(b4l, aVl + so + ndp * 2304 + ks2 * 32);
#pragma unroll
                for (int j = 0; j < 2; j++) {
                    int ntd = ndp * 2 + j;
#pragma unroll
                    for (int mi = 0; mi < 2; mi++) {
                        mma16816(oacc[mi][ntd], aPh[mi][ks2], b4h + 2 * j);
                        mma16816(oacc[mi][ntd], aPh[mi][ks2], b4l + 2 * j);
                        mma16816(oacc[mi][ntd], aPl[mi][ks2], b4h + 2 * j);
                    }
                }
            }
        }
        __syncthreads();
    }

    // reduce O across wn, write ctx packed hi/lo
    if (wn == 1) {
#pragma unroll
        for (int mi = 0; mi < 2; mi++)
#pragma unroll
            for (int ntd = 0; ntd < 8; ntd++) {
                int row = wm * 32 + mi * 16 + g;
                int col = ntd * 8 + tig * 2;
                *(float2*)&obuf[row * 68 + col] =
                    make_float2(oacc[mi][ntd][0], oacc[mi][ntd][1]);
                *(float2*)&obuf[(row + 8) * 68 + col] =
                    make_float2(oacc[mi][ntd][2], oacc[mi][ntd][3]);
            }
    }
    __syncthreads();
    if (wn == 0) {
        const int b = bh >> 4, h = bh & 15;
#pragma unroll
        for (int mi = 0; mi < 2; mi++)
#pragma unroll
            for (int ntd = 0; ntd < 8; ntd++) {
                int row = wm * 32 + mi * 16 + g;
                int col = ntd * 8 + tig * 2;
                float2 o0 = *(float2*)&obuf[row * 68 + col];
                float2 o1 = *(float2*)&obuf[(row + 8) * 68 + col];
                o0.x += oacc[mi][ntd][0]; o0.y += oacc[mi][ntd][1];
                o1.x += oacc[mi][ntd][2]; o1.y += oacc[mi][ntd][3];
                unsigned hi, lo;
                size_t base = ((size_t)(b * Sc + q0 + row)) * 512 + ((h * 64 + col) >> 1);
                split_pack2(o0.x, o0.y, hi, lo);
                g_ch[base] = hi; g_cl[base] = lo;
                size_t base8 = base + (size_t)8 * 512;
                split_pack2(o1.x, o1.y, hi, lo);
                g_ch[base8] = hi; g_cl[base8] = lo;
            }
    }
}

// ---------------------------------------------------------------------------
extern "C" void kernel_launch(void* const* d_in, const int* in_sizes, int n_in,
                              void* d_out, int out_size) {
    const float* v  = (const float*)d_in[0];
    const float* k  = (const float*)d_in[1];
    const float* q  = (const float*)d_in[2];
    const float* wq = (const float*)d_in[3];
    const float* bq = (const float*)d_in[4];
    const float* wk = (const float*)d_in[5];
    const float* bk = (const float*)d_in[6];
    const float* wv = (const float*)d_in[7];
    const float* bv = (const float*)d_in[8];
    const float* wo = (const float*)d_in[9];
    const float* bo = (const float*)d_in[10];

    float* out  = (float*)d_out;
    float* attn = out + (size_t)MROWS * DM;

    // attn smem: Q(2*128*72) + K(4*4608) + V(4*4608) bf16 + 768 floats
    const int attn_smem = (256 * QSTR + 8 * KSTAGE) * 2 + 768 * 4;   // 113664
    cudaFuncSetAttribute(fused_attn, cudaFuncAttributeMaxDynamicSharedMemorySize,
                         attn_smem);
    cudaFuncSetAttribute(proj_mma, cudaFuncAttributeMaxDynamicSharedMemorySize,
                         PROJ_SMEM);

    conv_x<<<3 * (MROWS * 512) / 256, 256>>>(q, k, v);
    conv_w<<<dim3(32, 32, 4), 256>>>(wq, wk, wv, wo);

    proj_mma<<<dim3(DM / 128, MROWS / 128, 3), 256, PROJ_SMEM>>>(
        bq, bk, bv, bo, out, -1);

    fused_attn<<<dim3(Sc / 128, BH), 256, attn_smem>>>(attn);

    proj_mma<<<dim3(DM / 128, MROWS / 128, 1), 256, PROJ_SMEM>>>(
        bq, bk, bv, bo, out, 3);
}